// round 4
// baseline (speedup 1.0000x reference)
#include <cuda_runtime.h>
#include <math.h>
#include <stdint.h>

// B=32, N=1024, DIM=768, GP=49
// ---------------- scratch ----------------
__device__ float g_qkv [(size_t)32768 * 2304];     // q|k|v rows, ld=2304 (tf32-rounded)
__device__ float g_S   [(size_t)32 * 1024 * 1024]; // scores -> attn (attn tf32-rounded)
__device__ float g_G   [(size_t)32 * 1024 * 1024];
__device__ float g_gw  [(size_t)32768 * 64];       // softmax groups, K padded to 64, rounded
__device__ float g_dots[(size_t)32768 * 128];      // V@w_gp, N padded to 128
__device__ float g_av  [(size_t)32768 * 768];      // attn@V (rounded)
__device__ float g_vt  [(size_t)32 * 768 * 1024];  // V^T (rounded)
__device__ float g_x   [(size_t)32768 * 768];      // x rounded to tf32
__device__ float g_wqkvT[(size_t)2304 * 768];      // rounded
__device__ float g_wprojT[(size_t)768 * 768];      // rounded
__device__ float g_wgpT [(size_t)128 * 768];       // rows 49..127 zero, rounded

// ---------------- helpers ----------------
static __device__ __forceinline__ float rtf(float f) {
    uint32_t r; asm("cvt.rna.tf32.f32 %0, %1;" : "=r"(r) : "f"(f));
    return __uint_as_float(r);
}
static __device__ __forceinline__ uint32_t s2u(const void* p) {
    uint32_t a;
    asm("{ .reg .u64 t; cvta.to.shared.u64 t, %1; cvt.u32.u64 %0, t; }" : "=r"(a) : "l"(p));
    return a;
}
#define CPA16(dst, src) \
    asm volatile("cp.async.cg.shared.global [%0], [%1], 16;" :: "r"(dst), "l"(src) : "memory")
#define CPA_COMMIT() asm volatile("cp.async.commit_group;" ::: "memory")
#define LDSM_X4(r, addr) \
    asm volatile("ldmatrix.sync.aligned.m8n8.x4.shared.b16 {%0,%1,%2,%3}, [%4];" \
        : "=r"((r)[0]), "=r"((r)[1]), "=r"((r)[2]), "=r"((r)[3]) : "r"(addr))

// ================= tf32 mma.sync GEMM =================
// C[M,N] = scale*(A[M,K] @ B[N,K]^T) (+bias[N]), optional tf32-rounding of output.
// A,B row-major K-major, tf32-pre-rounded. M,N mult of 128; K mult of 32.
// 256 threads, 128x128 block tile, warp grid 2(m) x 4(n) -> 64x32 per warp,
// K-tile 32, cp.async 2-stage, ldmatrix fragment loads.
__global__ void __launch_bounds__(256, 2) tgemm(
    const float* __restrict__ A, const float* __restrict__ B,
    const float* __restrict__ bias, float* __restrict__ C,
    int K, int lda, int ldb, int ldc,
    long long sA, long long sB, long long sC, float scale, int roundOut)
{
    extern __shared__ __align__(16) float sm[];   // [A0 4096f][B0 4096f][A1][B1]
    const uint32_t sbase = s2u(sm);

    const int tid = threadIdx.x;
    const int lane = tid & 31, wid = tid >> 5;
    const int wm = wid & 1, wn = wid >> 1;
    const int r4 = lane >> 2, q = lane & 3;
    const int m0 = blockIdx.y * 128, n0 = blockIdx.x * 128;

    A += (long long)blockIdx.z * sA + (long long)m0 * lda;
    B += (long long)blockIdx.z * sB + (long long)n0 * ldb;
    C += (long long)blockIdx.z * sC;

    // cp.async offsets: 4 chunks of 16B each for A and B, XOR-swizzled rows
    uint32_t swOff[4]; long long gA[4], gB[4];
    #pragma unroll
    for (int p = 0; p < 4; p++) {
        int idx = p * 256 + tid;
        int r = idx >> 3, c4 = idx & 7;
        swOff[p] = (uint32_t)(r * 128 + ((c4 ^ (r & 7)) << 4)); // bytes
        gA[p] = (long long)r * lda + c4 * 4;
        gB[p] = (long long)r * ldb + c4 * 4;
    }

    // ldmatrix row addressing: row = rowbase + (lane&15); chunk = 2*ks + (lane>>4).
    // Row bases are multiples of 8, so (row & 7) == (lane & 7) for ALL fragments.
    const int l15 = lane & 15;
    const int hi = lane >> 4;
    const int l7 = lane & 7;
    uint32_t aoff[4], boff[2];
    #pragma unroll
    for (int mi = 0; mi < 4; mi++) aoff[mi] = (uint32_t)((wm * 64 + mi * 16 + l15) * 128);
    #pragma unroll
    for (int bi = 0; bi < 2; bi++) boff[bi] = (uint32_t)((wn * 32 + bi * 16 + l15) * 128);

    const int nk = K / 32;

    // prologue: stage 0 -> buffer 0
    #pragma unroll
    for (int p = 0; p < 4; p++) {
        CPA16(sbase + swOff[p],         A + gA[p]);
        CPA16(sbase + 16384 + swOff[p], B + gB[p]);
    }
    CPA_COMMIT();

    float acc[4][4][4];
    #pragma unroll
    for (int i = 0; i < 4; i++)
        #pragma unroll
        for (int j = 0; j < 4; j++)
            #pragma unroll
            for (int v = 0; v < 4; v++) acc[i][j][v] = 0.0f;

    for (int kt = 0; kt < nk; kt++) {
        const int buf = kt & 1;
        if (kt + 1 < nk) {
            const float* An = A + (kt + 1) * 32;
            const float* Bn = B + (kt + 1) * 32;
            const uint32_t db = sbase + (uint32_t)((buf ^ 1) * 32768);
            #pragma unroll
            for (int p = 0; p < 4; p++) {
                CPA16(db + swOff[p],         An + gA[p]);
                CPA16(db + 16384 + swOff[p], Bn + gB[p]);
            }
            CPA_COMMIT();
            asm volatile("cp.async.wait_group 1;" ::: "memory");
        } else {
            asm volatile("cp.async.wait_group 0;" ::: "memory");
        }
        __syncthreads();

        const uint32_t Ab = sbase + (uint32_t)(buf * 32768);
        const uint32_t Bb = Ab + 16384;

        #pragma unroll
        for (int ks = 0; ks < 4; ks++) {
            const uint32_t swz = (uint32_t)(((2 * ks + hi) ^ l7) << 4);
            uint32_t a[4][4], bb[2][4];
            #pragma unroll
            for (int mi = 0; mi < 4; mi++) LDSM_X4(a[mi], Ab + aoff[mi] + swz);
            #pragma unroll
            for (int bi = 0; bi < 2; bi++) LDSM_X4(bb[bi], Bb + boff[bi] + swz);
            // bb[bi]: reg0 = b0(ni=2bi), reg1 = b0(ni=2bi+1), reg2 = b1(ni=2bi), reg3 = b1(ni=2bi+1)
            #pragma unroll
            for (int mi = 0; mi < 4; mi++)
                #pragma unroll
                for (int ni = 0; ni < 4; ni++)
                    asm volatile(
                        "mma.sync.aligned.m16n8k8.row.col.f32.tf32.tf32.f32 "
                        "{%0,%1,%2,%3}, {%4,%5,%6,%7}, {%8,%9}, {%0,%1,%2,%3};"
                        : "+f"(acc[mi][ni][0]), "+f"(acc[mi][ni][1]),
                          "+f"(acc[mi][ni][2]), "+f"(acc[mi][ni][3])
                        : "r"(a[mi][0]), "r"(a[mi][1]), "r"(a[mi][2]), "r"(a[mi][3]),
                          "r"(bb[ni >> 1][ni & 1]), "r"(bb[ni >> 1][2 + (ni & 1)]));
        }
        __syncthreads();
    }

    // epilogue: c0 (r4, 2q) c1 (r4, 2q+1) c2 (r4+8, 2q) c3 (r4+8, 2q+1)
    #pragma unroll
    for (int ni = 0; ni < 4; ni++) {
        const int col = n0 + wn * 32 + ni * 8 + 2 * q;
        float bx = 0.0f, by = 0.0f;
        if (bias) { bx = bias[col]; by = bias[col + 1]; }
        #pragma unroll
        for (int mi = 0; mi < 4; mi++) {
            const int row = m0 + wm * 64 + mi * 16 + r4;
            float2 v0, v1;
            v0.x = acc[mi][ni][0] * scale + bx;
            v0.y = acc[mi][ni][1] * scale + by;
            v1.x = acc[mi][ni][2] * scale + bx;
            v1.y = acc[mi][ni][3] * scale + by;
            if (roundOut) {
                v0.x = rtf(v0.x); v0.y = rtf(v0.y);
                v1.x = rtf(v1.x); v1.y = rtf(v1.y);
            }
            *(float2*)&C[(long long)row * ldc + col] = v0;
            *(float2*)&C[(long long)(row + 8) * ldc + col] = v1;
        }
    }
}

// ================= aux kernels =================
__global__ void round_x(const float* __restrict__ src, float* __restrict__ dst)
{
    const long long i = (long long)blockIdx.x * 256 + threadIdx.x;
    float4 v = ((const float4*)src)[i];
    v.x = rtf(v.x); v.y = rtf(v.y); v.z = rtf(v.z); v.w = rtf(v.w);
    ((float4*)dst)[i] = v;
}

// tiled transpose with tf32 rounding: dst[c][r] = round(src[r][c])
__global__ void ttrans(const float* __restrict__ src, float* __restrict__ dst,
                       int lds, int ldd, long long ss, long long sd)
{
    __shared__ float t[32][33];
    src += (long long)blockIdx.z * ss;
    dst += (long long)blockIdx.z * sd;
    const int r0 = blockIdx.x * 32, c0 = blockIdx.y * 32;
    const int x = threadIdx.x, y = threadIdx.y;
    #pragma unroll
    for (int i = y; i < 32; i += 8)
        t[i][x] = src[(long long)(r0 + i) * lds + c0 + x];
    __syncthreads();
    #pragma unroll
    for (int i = y; i < 32; i += 8)
        dst[(long long)(c0 + i) * ldd + r0 + x] = rtf(t[x][i]);
}

__global__ void wgp_pad(const float* __restrict__ w_gp, float* __restrict__ wgpT)
{
    int i = blockIdx.x * 256 + threadIdx.x;
    if (i < 128 * 768) {
        int g = i / 768, d = i % 768;
        wgpT[i] = (g < 49) ? rtf(w_gp[d * 49 + g]) : 0.0f;
    }
}

// softmax over dots[:,0:49] -> gw [32768,64] (cols 49..63 zero), tf32-rounded
__global__ void __launch_bounds__(128) gw_softmax(const float* __restrict__ dots,
                                                  float* __restrict__ gw)
{
    const int row = blockIdx.x * 4 + (threadIdx.x >> 5);
    const int t = threadIdx.x & 31;
    const float* d = dots + (long long)row * 128;
    float a = d[t];
    float b = (t < 17) ? d[32 + t] : -1e30f;
    float m = fmaxf(a, b);
    #pragma unroll
    for (int o = 16; o; o >>= 1) m = fmaxf(m, __shfl_xor_sync(0xffffffffu, m, o));
    float ea = __expf(a - m);
    float eb = (t < 17) ? __expf(b - m) : 0.0f;
    float s = ea + eb;
    #pragma unroll
    for (int o = 16; o; o >>= 1) s += __shfl_xor_sync(0xffffffffu, s, o);
    const float inv = 1.0f / s;
    float* g = gw + (long long)row * 64;
    g[t] = rtf(ea * inv);
    g[32 + t] = rtf(eb * inv);
}

// attn = exp(S-m)*G / (rowsum+eps), in-place on S, tf32-rounded output
__global__ void __launch_bounds__(256) attn_norm(float* __restrict__ S, const float* __restrict__ G)
{
    __shared__ float red[8];
    const long long row = blockIdx.x;
    float* s = S + row * 1024;
    const float* g = G + row * 1024;
    const int tid = threadIdx.x;

    float4 sv = ((const float4*)s)[tid];
    float m = fmaxf(fmaxf(sv.x, sv.y), fmaxf(sv.z, sv.w));
    #pragma unroll
    for (int o = 16; o; o >>= 1) m = fmaxf(m, __shfl_xor_sync(0xffffffffu, m, o));
    if ((tid & 31) == 0) red[tid >> 5] = m;
    __syncthreads();
    m = red[0];
    #pragma unroll
    for (int i = 1; i < 8; i++) m = fmaxf(m, red[i]);

    float4 gv = ((const float4*)g)[tid];
    float4 w;
    w.x = __expf(sv.x - m) * gv.x;
    w.y = __expf(sv.y - m) * gv.y;
    w.z = __expf(sv.z - m) * gv.z;
    w.w = __expf(sv.w - m) * gv.w;

    float ssum = w.x + w.y + w.z + w.w;
    #pragma unroll
    for (int o = 16; o; o >>= 1) ssum += __shfl_xor_sync(0xffffffffu, ssum, o);
    __syncthreads();
    if ((tid & 31) == 0) red[tid >> 5] = ssum;
    __syncthreads();
    float tot = 0.0f;
    #pragma unroll
    for (int i = 0; i < 8; i++) tot += red[i];

    const float inv = 1.0f / (tot + 1e-8f);
    w.x = rtf(w.x * inv); w.y = rtf(w.y * inv);
    w.z = rtf(w.z * inv); w.w = rtf(w.w * inv);
    ((float4*)s)[tid] = w;
}

// ================= launch =================
extern "C" void kernel_launch(void* const* d_in, const int* in_sizes, int n_in,
                              void* d_out, int out_size)
{
    const float* x      = (const float*)d_in[0];
    const float* w_qkv  = (const float*)d_in[1];
    const float* b_qkv  = (const float*)d_in[2];
    const float* w_proj = (const float*)d_in[3];
    const float* b_proj = (const float*)d_in[4];
    const float* w_gp   = (const float*)d_in[5];
    float* out = (float*)d_out;

    float *qkv, *S, *G, *gw, *dots, *av, *vt, *xr, *wqkvT, *wprojT, *wgpT;
    cudaGetSymbolAddress((void**)&qkv, g_qkv);
    cudaGetSymbolAddress((void**)&S, g_S);
    cudaGetSymbolAddress((void**)&G, g_G);
    cudaGetSymbolAddress((void**)&gw, g_gw);
    cudaGetSymbolAddress((void**)&dots, g_dots);
    cudaGetSymbolAddress((void**)&av, g_av);
    cudaGetSymbolAddress((void**)&vt, g_vt);
    cudaGetSymbolAddress((void**)&xr, g_x);
    cudaGetSymbolAddress((void**)&wqkvT, g_wqkvT);
    cudaGetSymbolAddress((void**)&wprojT, g_wprojT);
    cudaGetSymbolAddress((void**)&wgpT, g_wgpT);

    const int SMEM = 65536;
    cudaFuncSetAttribute(tgemm, cudaFuncAttributeMaxDynamicSharedMemorySize, SMEM);

    const float scaleS = 1.0f / sqrtf(768.0f);
    dim3 tb(32, 8);

    // producers: round everything that feeds an MMA operand to tf32
    round_x<<<24576, 256>>>(x, xr);
    ttrans<<<dim3(24, 72, 1), tb>>>(w_qkv, wqkvT, 2304, 768, 0, 0);
    ttrans<<<dim3(24, 24, 1), tb>>>(w_proj, wprojT, 768, 768, 0, 0);
    wgp_pad<<<384, 256>>>(w_gp, wgpT);

    // qkv = x @ w_qkv + b   [32768,2304] K=768  (rounded)
    tgemm<<<dim3(18, 256, 1), 256, SMEM>>>(
        xr, wqkvT, b_qkv, qkv, 768, 768, 768, 2304, 0, 0, 0, 1.0f, 1);

    // vt = V^T per batch
    ttrans<<<dim3(32, 24, 32), tb>>>(qkv + 1536, vt, 2304, 1024, 1024LL * 2304, 768LL * 1024);

    // dots = V @ w_gp  (N padded 128)
    tgemm<<<dim3(1, 256, 1), 256, SMEM>>>(
        qkv + 1536, wgpT, nullptr, dots, 768, 2304, 768, 128, 0, 0, 0, 1.0f, 0);

    // S = Q @ K^T * scale  batched
    tgemm<<<dim3(8, 8, 32), 256, SMEM>>>(
        qkv, qkv + 768, nullptr, S, 768, 2304, 2304, 1024,
        1024LL * 2304, 1024LL * 2304, 1024LL * 1024, scaleS, 0);

    gw_softmax<<<8192, 128>>>(dots, gw);

    // G = gw @ gw^T  (K padded 64)
    tgemm<<<dim3(8, 8, 32), 256, SMEM>>>(
        gw, gw, nullptr, G, 64, 64, 64, 1024,
        1024LL * 64, 1024LL * 64, 1024LL * 1024, 1.0f, 0);

    attn_norm<<<32768, 256>>>(S, G);

    // av = attn @ V  (rounded)
    tgemm<<<dim3(6, 8, 32), 256, SMEM>>>(
        S, vt, nullptr, av, 1024, 1024, 1024, 768,
        1024LL * 1024, 768LL * 1024, 1024LL * 768, 1.0f, 1);

    // out = av @ w_proj + b  (final, not rounded)
    tgemm<<<dim3(6, 256, 1), 256, SMEM>>>(
        av, wprojT, b_proj, out, 768, 768, 768, 768, 0, 0, 0, 1.0f, 0);
}

// round 5
// speedup vs baseline: 1.9400x; 1.9400x over previous
#include <cuda_runtime.h>
#include <cuda_fp16.h>
#include <math.h>
#include <stdint.h>

// B=32, N=1024, DIM=768, GP=49
// ---------------- scratch ----------------
__device__ __half g_xh   [(size_t)32768 * 768];
__device__ __half g_qkvh [(size_t)32768 * 2304];     // q|k|v fp16, ld=2304
__device__ float  g_S    [(size_t)32 * 1024 * 1024]; // scores fp32
__device__ float  g_G    [(size_t)32 * 1024 * 1024]; // gw@gw^T fp32
__device__ __half g_attnh[(size_t)32 * 1024 * 1024]; // normalized attn fp16
__device__ __half g_gwh  [(size_t)32768 * 64];       // softmax groups, K padded 64
__device__ float  g_dots [(size_t)32768 * 128];      // V@w_gp fp32, N padded 128
__device__ __half g_avh  [(size_t)32768 * 768];
__device__ __half g_vth  [(size_t)32 * 768 * 1024];  // V^T fp16
__device__ __half g_wqkvT [(size_t)2304 * 768];
__device__ __half g_wprojT[(size_t)768 * 768];
__device__ __half g_wgpT  [(size_t)128 * 768];       // rows 49..127 zero

// ---------------- helpers ----------------
static __device__ __forceinline__ uint32_t s2u(const void* p) {
    uint32_t a;
    asm("{ .reg .u64 t; cvta.to.shared.u64 t, %1; cvt.u32.u64 %0, t; }" : "=r"(a) : "l"(p));
    return a;
}
#define CPA16(dst, src) \
    asm volatile("cp.async.cg.shared.global [%0], [%1], 16;" :: "r"(dst), "l"(src) : "memory")
#define CPA_COMMIT() asm volatile("cp.async.commit_group;" ::: "memory")
#define LDSM_X4(r, addr) \
    asm volatile("ldmatrix.sync.aligned.m8n8.x4.shared.b16 {%0,%1,%2,%3}, [%4];" \
        : "=r"((r)[0]), "=r"((r)[1]), "=r"((r)[2]), "=r"((r)[3]) : "r"(addr))

// ================= fp16 mma.sync GEMM =================
// C[M,N] = scale*(A[M,K] @ B[N,K]^T) (+bias[N]); C fp32 or fp16 (OUTH).
// A,B fp16 row-major K-major. M,N mult of 128; K mult of 64.
// 256 threads, 128x128 tile, warp grid 2(m)x4(n) -> 64x32/warp,
// K-tile 64 halves (128B rows), cp.async 2-stage, ldmatrix fragments.
template<bool OUTH>
__global__ void __launch_bounds__(256) hgemm(
    const __half* __restrict__ A, const __half* __restrict__ B,
    const float* __restrict__ bias, void* __restrict__ Cv,
    int K, int lda, int ldb, int ldc,
    long long sA, long long sB, long long sC, float scale)
{
    extern __shared__ __align__(16) char sm[];   // [A0 16K][B0 16K][A1][B1] bytes
    const uint32_t sbase = s2u(sm);

    const int tid = threadIdx.x;
    const int lane = tid & 31, wid = tid >> 5;
    const int wm = wid & 1, wn = wid >> 1;
    const int r4 = lane >> 2, q = lane & 3;
    const int m0 = blockIdx.y * 128, n0 = blockIdx.x * 128;

    A += (long long)blockIdx.z * sA + (long long)m0 * lda;
    B += (long long)blockIdx.z * sB + (long long)n0 * ldb;

    // cp.async: tile = 128 rows x 64 halves (128B); 8 x 16B chunks/row, XOR swizzle
    uint32_t swOff[4]; long long gA[4], gB[4];
    #pragma unroll
    for (int p = 0; p < 4; p++) {
        int idx = p * 256 + tid;
        int r = idx >> 3, c = idx & 7;
        swOff[p] = (uint32_t)(r * 128 + ((c ^ (r & 7)) << 4));
        gA[p] = (long long)r * lda + c * 8;
        gB[p] = (long long)r * ldb + c * 8;
    }

    // ldmatrix addressing (row bases mult of 8 -> swizzle XOR is uniform = lane&7)
    const int l7 = lane & 7;
    const int arow = l7 + (((lane >> 3) & 1) << 3);  // A: mats {m0-7,m8-15,m0-7,m8-15}
    const int achk = lane >> 4;                      //    chunks {0,0,1,1} (+2ks)
    const int brow = l7 + ((lane >> 4) << 3);        // B: mats {n0-7,n0-7,n8-15,n8-15}
    const int bchk = (lane >> 3) & 1;                //    chunks {0,1,0,1} (+2ks)
    uint32_t aoff[4], boff[2];
    #pragma unroll
    for (int mi = 0; mi < 4; mi++) aoff[mi] = (uint32_t)((wm * 64 + mi * 16 + arow) * 128);
    #pragma unroll
    for (int bi = 0; bi < 2; bi++) boff[bi] = (uint32_t)((wn * 32 + bi * 16 + brow) * 128);

    const int nk = K / 64;

    // prologue
    #pragma unroll
    for (int p = 0; p < 4; p++) {
        CPA16(sbase + swOff[p],         A + gA[p]);
        CPA16(sbase + 16384 + swOff[p], B + gB[p]);
    }
    CPA_COMMIT();

    float acc[4][4][4];
    #pragma unroll
    for (int i = 0; i < 4; i++)
        #pragma unroll
        for (int j = 0; j < 4; j++)
            #pragma unroll
            for (int v = 0; v < 4; v++) acc[i][j][v] = 0.0f;

    for (int kt = 0; kt < nk; kt++) {
        const int buf = kt & 1;
        if (kt + 1 < nk) {
            const __half* An = A + (kt + 1) * 64;
            const __half* Bn = B + (kt + 1) * 64;
            const uint32_t db = sbase + (uint32_t)((buf ^ 1) * 32768);
            #pragma unroll
            for (int p = 0; p < 4; p++) {
                CPA16(db + swOff[p],         An + gA[p]);
                CPA16(db + 16384 + swOff[p], Bn + gB[p]);
            }
            CPA_COMMIT();
            asm volatile("cp.async.wait_group 1;" ::: "memory");
        } else {
            asm volatile("cp.async.wait_group 0;" ::: "memory");
        }
        __syncthreads();

        const uint32_t Ab = sbase + (uint32_t)(buf * 32768);
        const uint32_t Bb = Ab + 16384;

        #pragma unroll
        for (int ks = 0; ks < 4; ks++) {
            const uint32_t swzA = (uint32_t)(((2 * ks + achk) ^ l7) << 4);
            const uint32_t swzB = (uint32_t)(((2 * ks + bchk) ^ l7) << 4);
            uint32_t a[4][4], bb[2][4];
            #pragma unroll
            for (int mi = 0; mi < 4; mi++) LDSM_X4(a[mi], Ab + aoff[mi] + swzA);
            #pragma unroll
            for (int bi = 0; bi < 2; bi++) LDSM_X4(bb[bi], Bb + boff[bi] + swzB);
            // bb[bi]: r0=b0(n low8), r1=b1(n low8), r2=b0(n high8), r3=b1(n high8)
            #pragma unroll
            for (int mi = 0; mi < 4; mi++)
                #pragma unroll
                for (int ni = 0; ni < 4; ni++)
                    asm volatile(
                        "mma.sync.aligned.m16n8k16.row.col.f32.f16.f16.f32 "
                        "{%0,%1,%2,%3}, {%4,%5,%6,%7}, {%8,%9}, {%0,%1,%2,%3};"
                        : "+f"(acc[mi][ni][0]), "+f"(acc[mi][ni][1]),
                          "+f"(acc[mi][ni][2]), "+f"(acc[mi][ni][3])
                        : "r"(a[mi][0]), "r"(a[mi][1]), "r"(a[mi][2]), "r"(a[mi][3]),
                          "r"(bb[ni >> 1][(ni & 1) << 1]), "r"(bb[ni >> 1][((ni & 1) << 1) + 1]));
        }
        __syncthreads();
    }

    // epilogue: C frag c0 (r4,2q) c1 (r4,2q+1) c2 (r4+8,2q) c3 (r4+8,2q+1)
    float* Cf = (float*)Cv + blockIdx.z * sC;
    __half* Ch = (__half*)Cv + blockIdx.z * sC;
    #pragma unroll
    for (int ni = 0; ni < 4; ni++) {
        const int col = n0 + wn * 32 + ni * 8 + 2 * q;
        float bx = 0.0f, by = 0.0f;
        if (bias) { bx = bias[col]; by = bias[col + 1]; }
        #pragma unroll
        for (int mi = 0; mi < 4; mi++) {
            const int row = m0 + wm * 64 + mi * 16 + r4;
            float2 v0, v1;
            v0.x = acc[mi][ni][0] * scale + bx;
            v0.y = acc[mi][ni][1] * scale + by;
            v1.x = acc[mi][ni][2] * scale + bx;
            v1.y = acc[mi][ni][3] * scale + by;
            if (OUTH) {
                *(__half2*)&Ch[(long long)row * ldc + col]       = __float22half2_rn(v0);
                *(__half2*)&Ch[(long long)(row + 8) * ldc + col] = __float22half2_rn(v1);
            } else {
                *(float2*)&Cf[(long long)row * ldc + col]       = v0;
                *(float2*)&Cf[(long long)(row + 8) * ldc + col] = v1;
            }
        }
    }
}

// ================= aux kernels =================
__global__ void conv_f2h(const float* __restrict__ src, __half* __restrict__ dst)
{
    const long long i = (long long)blockIdx.x * 256 + threadIdx.x;
    float4 v = ((const float4*)src)[i];
    __half2* d = (__half2*)dst;
    d[2 * i]     = __float22half2_rn(make_float2(v.x, v.y));
    d[2 * i + 1] = __float22half2_rn(make_float2(v.z, v.w));
}

// transpose fp32 -> fp16: dst[c][r] = h(src[r][c])   (weights)
__global__ void trans_f2h(const float* __restrict__ src, __half* __restrict__ dst,
                          int lds, int ldd)
{
    __shared__ float t[32][33];
    const int r0 = blockIdx.x * 32, c0 = blockIdx.y * 32;
    const int x = threadIdx.x, y = threadIdx.y;
    #pragma unroll
    for (int i = y; i < 32; i += 8)
        t[i][x] = src[(long long)(r0 + i) * lds + c0 + x];
    __syncthreads();
    #pragma unroll
    for (int i = y; i < 32; i += 8)
        dst[(long long)(c0 + i) * ldd + r0 + x] = __float2half(t[x][i]);
}

// transpose fp16 -> fp16 batched (V^T)
__global__ void trans_h2h(const __half* __restrict__ src, __half* __restrict__ dst,
                          int lds, int ldd, long long ss, long long sd)
{
    __shared__ __half t[32][33];
    src += (long long)blockIdx.z * ss;
    dst += (long long)blockIdx.z * sd;
    const int r0 = blockIdx.x * 32, c0 = blockIdx.y * 32;
    const int x = threadIdx.x, y = threadIdx.y;
    #pragma unroll
    for (int i = y; i < 32; i += 8)
        t[i][x] = src[(long long)(r0 + i) * lds + c0 + x];
    __syncthreads();
    #pragma unroll
    for (int i = y; i < 32; i += 8)
        dst[(long long)(c0 + i) * ldd + r0 + x] = t[x][i];
}

__global__ void wgp_pad(const float* __restrict__ w_gp, __half* __restrict__ wgpT)
{
    int i = blockIdx.x * 256 + threadIdx.x;
    if (i < 128 * 768) {
        int g = i / 768, d = i % 768;
        wgpT[i] = (g < 49) ? __float2half(w_gp[d * 49 + g]) : __float2half(0.0f);
    }
}

// softmax over dots[:,0:49] -> gwh [32768,64] fp16 (cols 49..63 zero)
__global__ void __launch_bounds__(128) gw_softmax(const float* __restrict__ dots,
                                                  __half* __restrict__ gw)
{
    const int row = blockIdx.x * 4 + (threadIdx.x >> 5);
    const int t = threadIdx.x & 31;
    const float* d = dots + (long long)row * 128;
    float a = d[t];
    float b = (t < 17) ? d[32 + t] : -1e30f;
    float m = fmaxf(a, b);
    #pragma unroll
    for (int o = 16; o; o >>= 1) m = fmaxf(m, __shfl_xor_sync(0xffffffffu, m, o));
    float ea = __expf(a - m);
    float eb = (t < 17) ? __expf(b - m) : 0.0f;
    float s = ea + eb;
    #pragma unroll
    for (int o = 16; o; o >>= 1) s += __shfl_xor_sync(0xffffffffu, s, o);
    const float inv = 1.0f / s;
    __half* g = gw + (long long)row * 64;
    g[t] = __float2half(ea * inv);
    g[32 + t] = __float2half(eb * inv);
}

// attn = exp(S-m)*G / (rowsum+eps) -> fp16
__global__ void __launch_bounds__(256) attn_norm(
    const float* __restrict__ S, const float* __restrict__ G, __half* __restrict__ attn)
{
    __shared__ float red[8];
    const long long row = blockIdx.x;
    const float* s = S + row * 1024;
    const float* g = G + row * 1024;
    const int tid = threadIdx.x;

    float4 sv = ((const float4*)s)[tid];
    float m = fmaxf(fmaxf(sv.x, sv.y), fmaxf(sv.z, sv.w));
    #pragma unroll
    for (int o = 16; o; o >>= 1) m = fmaxf(m, __shfl_xor_sync(0xffffffffu, m, o));
    if ((tid & 31) == 0) red[tid >> 5] = m;
    __syncthreads();
    m = red[0];
    #pragma unroll
    for (int i = 1; i < 8; i++) m = fmaxf(m, red[i]);

    float4 gv = ((const float4*)g)[tid];
    float4 w;
    w.x = __expf(sv.x - m) * gv.x;
    w.y = __expf(sv.y - m) * gv.y;
    w.z = __expf(sv.z - m) * gv.z;
    w.w = __expf(sv.w - m) * gv.w;

    float ssum = w.x + w.y + w.z + w.w;
    #pragma unroll
    for (int o = 16; o; o >>= 1) ssum += __shfl_xor_sync(0xffffffffu, ssum, o);
    __syncthreads();
    if ((tid & 31) == 0) red[tid >> 5] = ssum;
    __syncthreads();
    float tot = 0.0f;
    #pragma unroll
    for (int i = 0; i < 8; i++) tot += red[i];

    const float inv = 1.0f / (tot + 1e-8f);
    __half2* o2 = (__half2*)(attn + row * 1024);
    o2[2 * tid]     = __float22half2_rn(make_float2(w.x * inv, w.y * inv));
    o2[2 * tid + 1] = __float22half2_rn(make_float2(w.z * inv, w.w * inv));
}

// ================= launch =================
extern "C" void kernel_launch(void* const* d_in, const int* in_sizes, int n_in,
                              void* d_out, int out_size)
{
    const float* x      = (const float*)d_in[0];
    const float* w_qkv  = (const float*)d_in[1];
    const float* b_qkv  = (const float*)d_in[2];
    const float* w_proj = (const float*)d_in[3];
    const float* b_proj = (const float*)d_in[4];
    const float* w_gp   = (const float*)d_in[5];
    float* out = (float*)d_out;

    __half *xh, *qkvh, *attnh, *gwh, *avh, *vth, *wqkvTh, *wprojTh, *wgpTh;
    float *S, *G, *dots;
    cudaGetSymbolAddress((void**)&xh, g_xh);
    cudaGetSymbolAddress((void**)&qkvh, g_qkvh);
    cudaGetSymbolAddress((void**)&S, g_S);
    cudaGetSymbolAddress((void**)&G, g_G);
    cudaGetSymbolAddress((void**)&attnh, g_attnh);
    cudaGetSymbolAddress((void**)&gwh, g_gwh);
    cudaGetSymbolAddress((void**)&dots, g_dots);
    cudaGetSymbolAddress((void**)&avh, g_avh);
    cudaGetSymbolAddress((void**)&vth, g_vth);
    cudaGetSymbolAddress((void**)&wqkvTh, g_wqkvT);
    cudaGetSymbolAddress((void**)&wprojTh, g_wprojT);
    cudaGetSymbolAddress((void**)&wgpTh, g_wgpT);

    const int SMEM = 65536;
    cudaFuncSetAttribute(hgemm<true>,  cudaFuncAttributeMaxDynamicSharedMemorySize, SMEM);
    cudaFuncSetAttribute(hgemm<false>, cudaFuncAttributeMaxDynamicSharedMemorySize, SMEM);

    const float scaleS = 1.0f / sqrtf(768.0f);
    dim3 tb(32, 8);

    // producers: convert operands to fp16
    conv_f2h<<<24576, 256>>>(x, xh);
    trans_f2h<<<dim3(24, 72), tb>>>(w_qkv, wqkvTh, 2304, 768);
    trans_f2h<<<dim3(24, 24), tb>>>(w_proj, wprojTh, 768, 768);
    wgp_pad<<<384, 256>>>(w_gp, wgpTh);

    // qkv = x @ w_qkv + b   [32768,2304] K=768 -> fp16
    hgemm<true><<<dim3(18, 256, 1), 256, SMEM>>>(
        xh, wqkvTh, b_qkv, qkvh, 768, 768, 768, 2304, 0, 0, 0, 1.0f);

    // vt = V^T per batch
    trans_h2h<<<dim3(32, 24, 32), tb>>>(qkvh + 1536, vth, 2304, 1024,
                                        1024LL * 2304, 768LL * 1024);

    // dots = V @ w_gp (N padded 128) -> fp32
    hgemm<false><<<dim3(1, 256, 1), 256, SMEM>>>(
        qkvh + 1536, wgpTh, nullptr, dots, 768, 2304, 768, 128, 0, 0, 0, 1.0f);

    // S = Q @ K^T * scale -> fp32, batched
    hgemm<false><<<dim3(8, 8, 32), 256, SMEM>>>(
        qkvh, qkvh + 768, nullptr, S, 768, 2304, 2304, 1024,
        1024LL * 2304, 1024LL * 2304, 1024LL * 1024, scaleS);

    gw_softmax<<<8192, 128>>>(dots, gwh);

    // G = gw @ gw^T (K padded 64) -> fp32
    hgemm<false><<<dim3(8, 8, 32), 256, SMEM>>>(
        gwh, gwh, nullptr, G, 64, 64, 64, 1024,
        1024LL * 64, 1024LL * 64, 1024LL * 1024, 1.0f);

    attn_norm<<<32768, 256>>>(S, G, attnh);

    // av = attn @ V -> fp16
    hgemm<true><<<dim3(6, 8, 32), 256, SMEM>>>(
        attnh, vth, nullptr, avh, 1024, 1024, 1024, 768,
        1024LL * 1024, 768LL * 1024, 1024LL * 768, 1.0f);

    // out = av @ w_proj + b -> fp32 (final)
    hgemm<false><<<dim3(6, 256, 1), 256, SMEM>>>(
        avh, wprojTh, b_proj, out, 768, 768, 768, 768, 0, 0, 0, 1.0f);
}